// round 5
// baseline (speedup 1.0000x reference)
#include <cuda_runtime.h>
#include <cuda_bf16.h>
#include <stdint.h>

#define BATCH 32
#define NPOS  8732
#define CLS_OFF ((size_t)BATCH * NPOS * 4)

__device__ __nv_bfloat16 g_xt_hi[37412864];
__device__ __nv_bfloat16 g_xt_lo[37412864];
__device__ __nv_bfloat16 g_wt_hi[12695040];
__device__ __nv_bfloat16 g_wt_lo[12695040];

__device__ __forceinline__ uint32_t smem_u32(const void* p) {
    uint32_t r;
    asm("{ .reg .u64 t; cvta.to.shared.u64 t, %1; cvt.u32.u64 %0, t; }" : "=r"(r) : "l"(p));
    return r;
}
__device__ __forceinline__ void cp16(uint32_t dst, const void* src, uint32_t sz) {
    asm volatile("cp.async.cg.shared.global [%0], [%1], 16, %2;"
                 :: "r"(dst), "l"(src), "r"(sz) : "memory");
}
__device__ __forceinline__ void cp_commit() { asm volatile("cp.async.commit_group;" ::: "memory"); }
__device__ __forceinline__ void cp_wait1()  { asm volatile("cp.async.wait_group 1;" ::: "memory"); }
__device__ __forceinline__ void cp_wait0()  { asm volatile("cp.async.wait_group 0;" ::: "memory"); }
__device__ __forceinline__ void ldsm4(uint32_t* r, uint32_t a) {
    asm volatile("ldmatrix.sync.aligned.m8n8.x4.shared.b16 {%0,%1,%2,%3}, [%4];"
                 : "=r"(r[0]), "=r"(r[1]), "=r"(r[2]), "=r"(r[3]) : "r"(a));
}
__device__ __forceinline__ void mma_bf16(float* d, const uint32_t* a, uint32_t b0, uint32_t b1) {
    asm volatile("mma.sync.aligned.m16n8k16.row.col.f32.bf16.bf16.f32 "
                 "{%0,%1,%2,%3}, {%4,%5,%6,%7}, {%8,%9}, {%0,%1,%2,%3};"
                 : "+f"(d[0]), "+f"(d[1]), "+f"(d[2]), "+f"(d[3])
                 : "r"(a[0]), "r"(a[1]), "r"(a[2]), "r"(a[3]), "r"(b0), "r"(b1));
}

__global__ void noop_kernel() {}

// ---- prep 1: activation transpose [n][c][p] -> [n][p][c], bf16 split ----
__global__ void transpose_kernel(const float* __restrict__ x, size_t xoff, int C, int HW) {
    __shared__ float tile[32][33];
    const int n = blockIdx.z, p0 = blockIdx.x * 32, c0 = blockIdx.y * 32;
    const int tx = threadIdx.x, ty = threadIdx.y;
    const float* xb = x + (size_t)n * C * HW;
#pragma unroll
    for (int k = 0; k < 4; k++) {
        int c = c0 + ty + 8 * k, p = p0 + tx;
        tile[ty + 8 * k][tx] = (p < HW) ? xb[(size_t)c * HW + p] : 0.f;
    }
    __syncthreads();
#pragma unroll
    for (int k = 0; k < 4; k++) {
        int p = p0 + ty + 8 * k, c = c0 + tx;
        if (p < HW) {
            float v = tile[tx][ty + 8 * k];
            __nv_bfloat16 hi = __float2bfloat16(v);
            __nv_bfloat16 lo = __float2bfloat16(v - __bfloat162float(hi));
            size_t o = xoff + ((size_t)n * HW + p) * C + c;
            g_xt_hi[o] = hi; g_xt_lo[o] = lo;
        }
    }
}

// ---- prep 2: weights -> [tap][o][c], bf16 split (o = reg then cls) ----
__global__ void pack_w_kernel(const float* __restrict__ regw, const float* __restrict__ clsw,
                              size_t woff, int C, int A4, int Otot) {
    int idx = blockIdx.x * blockDim.x + threadIdx.x;
    if (idx >= Otot * C) return;
    int c = idx % C, o = idx / C;
    const float* src = (o < A4) ? (regw + ((size_t)o * C + c) * 9)
                                : (clsw + ((size_t)(o - A4) * C + c) * 9);
#pragma unroll
    for (int tap = 0; tap < 9; tap++) {
        float v = src[tap];
        __nv_bfloat16 hi = __float2bfloat16(v);
        __nv_bfloat16 lo = __float2bfloat16(v - __bfloat162float(hi));
        size_t d = woff + ((size_t)tap * Otot + o) * C + c;
        g_wt_hi[d] = hi; g_wt_lo[d] = lo;
    }
}

// ---- main GEMM: mma.sync bf16 (3-term split), CTA 128x128, kchunk 32 ----
// 4 warps, warp tile 64x64. smem stage: Ah|Al|Bh|Bl @ 10240B each (80B rows).
#define STG 40960
#define ROWB 80

__global__ __launch_bounds__(128, 2)
void gemm_kernel(size_t xoff, size_t woff,
                 const float* __restrict__ regb, const float* __restrict__ clsb,
                 float* __restrict__ out,
                 int C, int H, int W, int A, int Otot, int P, int M) {
    extern __shared__ char dsm[];
    const uint32_t sb = smem_u32(dsm);

    const int HW = H * W, KC = C >> 5, nchunks = 9 * KC;
    const int t = threadIdx.x, warp = t >> 5, lane = t & 31;
    const int m0 = blockIdx.y * 128, o0 = blockIdx.x * 128;
    const int MT = BATCH * M, A4 = 4 * A;
    const int mwarp = warp >> 1, nwarp = warp & 1;

    // loader: thread t owns A row t and B row t (64B per plane = 4 cp16)
    const int r = t;
    const int ma = m0 + r;
    const bool avalid = (ma < MT);
    const int mm = avalid ? ma : 0;
    const int na = mm / M, pa = mm - na * M;
    const int ah_ = pa / W, aw_ = pa - ah_ * W;
    const size_t a_nbase = (size_t)na * HW * C;
    const int ob = o0 + r;
    const bool bvalid = (ob < Otot);
    const size_t b_obase = (size_t)(bvalid ? ob : 0) * C;
    const size_t OC = (size_t)Otot * C;
    const uint32_t dst_r = (uint32_t)r * ROWB;

    float acc[4][8][4];
#pragma unroll
    for (int i = 0; i < 4; i++)
#pragma unroll
        for (int j = 0; j < 8; j++)
#pragma unroll
            for (int k = 0; k < 4; k++) acc[i][j][k] = 0.f;

    const uint32_t a_lmrow = (uint32_t)(mwarp * 64 + (lane & 15)) * ROWB + ((lane >> 4) * 16);
    const int nl = (lane & 7) + ((lane >> 4) << 3);
    const uint32_t b_lmrow = (uint32_t)(nwarp * 64 + nl) * ROWB + (((lane >> 3) & 1) * 16);

#define LOAD_CHUNK(ch, s) {                                                         \
    const int tap = (ch) / KC, ck = (ch) - tap * KC;                                \
    const int dy = tap / 3 - 1, dx = tap % 3 - 1;                                   \
    const int hh = ah_ + dy, ww = aw_ + dx;                                         \
    const bool aok = avalid && hh >= 0 && hh < H && ww >= 0 && ww < W;              \
    const size_t asrc = xoff + a_nbase + (size_t)(aok ? (hh * W + ww) : 0) * C      \
                        + (ck << 5);                                                \
    const size_t bsrc = woff + (size_t)tap * OC + b_obase + (ck << 5);              \
    const uint32_t az = aok ? 16u : 0u, bz = bvalid ? 16u : 0u;                     \
    const uint32_t d0 = sb + (s) * STG + dst_r;                                     \
    _Pragma("unroll")                                                               \
    for (int c = 0; c < 4; c++) {                                                   \
        cp16(d0 + c * 16,         g_xt_hi + asrc + c * 8, az);                      \
        cp16(d0 + 10240 + c * 16, g_xt_lo + asrc + c * 8, az);                      \
        cp16(d0 + 20480 + c * 16, g_wt_hi + bsrc + c * 8, bz);                      \
        cp16(d0 + 30720 + c * 16, g_wt_lo + bsrc + c * 8, bz);                      \
    }                                                                               \
    cp_commit(); }

    LOAD_CHUNK(0, 0)

    for (int ch = 0; ch < nchunks; ch++) {
        const int s = ch & 1;
        if (ch + 1 < nchunks) { LOAD_CHUNK(ch + 1, s ^ 1) cp_wait1(); }
        else cp_wait0();
        __syncthreads();

        const uint32_t base = sb + s * STG;
#pragma unroll
        for (int ks = 0; ks < 2; ks++) {
            const uint32_t ko = ks * 32;
            uint32_t ahf[4][4], alf[4][4];
#pragma unroll
            for (int mt = 0; mt < 4; mt++) {
                ldsm4(ahf[mt], base + a_lmrow + mt * (16 * ROWB) + ko);
                ldsm4(alf[mt], base + 10240 + a_lmrow + mt * (16 * ROWB) + ko);
            }
#pragma unroll
            for (int bt = 0; bt < 4; bt++) {
                uint32_t bhf[4], blf[4];
                ldsm4(bhf, base + 20480 + b_lmrow + bt * (16 * ROWB) + ko);
                ldsm4(blf, base + 30720 + b_lmrow + bt * (16 * ROWB) + ko);
#pragma unroll
                for (int mt = 0; mt < 4; mt++) {
#pragma unroll
                    for (int su = 0; su < 2; su++) {
                        float* d = acc[mt][bt * 2 + su];
                        mma_bf16(d, ahf[mt], bhf[su * 2], bhf[su * 2 + 1]);
                        mma_bf16(d, ahf[mt], blf[su * 2], blf[su * 2 + 1]);
                        mma_bf16(d, alf[mt], bhf[su * 2], bhf[su * 2 + 1]);
                    }
                }
            }
        }
        __syncthreads();
    }

    // ---- epilogue: bias + scatter ----
    float* bbox = out;
    float* cls  = out + CLS_OFF;
#pragma unroll
    for (int mt = 0; mt < 4; mt++) {
#pragma unroll
        for (int half = 0; half < 2; half++) {
            const int m = m0 + mwarp * 64 + mt * 16 + (lane >> 2) + half * 8;
            if (m >= MT) continue;
            const int n = m / M, p = m - n * M;
            const size_t obase = (size_t)n * NPOS + P + (size_t)p * A;
#pragma unroll
            for (int nt = 0; nt < 8; nt++) {
#pragma unroll
                for (int e = 0; e < 2; e++) {
                    const int o = o0 + nwarp * 64 + nt * 8 + (lane & 3) * 2 + e;
                    if (o >= Otot) continue;
                    float v = acc[mt][nt][half * 2 + e];
                    if (o < A4) {
                        v += regb[o];
                        bbox[(obase + (o >> 2)) * 4 + (o & 3)] = v;
                    } else {
                        const int q = o - A4;
                        v += clsb[q];
                        const int a = q / 91;
                        cls[(obase + a) * 91 + (q - a * 91)] = v;
                    }
                }
            }
        }
    }
}

// ------------------------------- launch ------------------------------------
extern "C" void kernel_launch(void* const* d_in, const int* in_sizes, int n_in,
                              void* d_out, int out_size) {
    static const int    Cs[6]   = {512, 1024, 512, 256, 256, 256};
    static const int    Ss[6]   = {38, 19, 10, 5, 3, 1};
    static const int    Aa[6]   = {4, 6, 6, 6, 4, 4};
    static const int    Ps[6]   = {0, 5776, 7942, 8542, 8692, 8728};
    static const size_t XOFF[6] = {0, 23658496, 35487744, 37126144, 37330944, 37404672};
    static const size_t WOFF[6] = {0, 1751040, 7004160, 9630720, 10944000, 11819520};
    const int SMEM = 2 * STG;

    cudaFuncSetAttribute(gemm_kernel, cudaFuncAttributeMaxDynamicSharedMemorySize, SMEM);
    float* out = (float*)d_out;

    auto prep = [&](int i) {
        const int C = Cs[i], S = Ss[i], A = Aa[i];
        const int HW = S * S, Otot = 95 * A, A4 = 4 * A;
        const float* feat = (const float*)d_in[5 * i + 0];
        const float* clsw = (const float*)d_in[5 * i + 1];
        const float* regw = (const float*)d_in[5 * i + 3];
        dim3 tg((HW + 31) / 32, C / 32, BATCH);
        transpose_kernel<<<tg, dim3(32, 8)>>>(feat, XOFF[i], C, HW);
        int tot = Otot * C;
        pack_w_kernel<<<(tot + 255) / 256, 256>>>(regw, clsw, WOFF[i], C, A4, Otot);
    };
    auto gemm = [&](int i) {
        const int C = Cs[i], S = Ss[i], A = Aa[i];
        const int Otot = 95 * A, M = S * S, MT = BATCH * M;
        const float* clsb = (const float*)d_in[5 * i + 2];
        const float* regb = (const float*)d_in[5 * i + 4];
        dim3 grid((Otot + 127) / 128, (MT + 127) / 128);
        gemm_kernel<<<grid, 128, SMEM>>>(XOFF[i], WOFF[i], regb, clsb, out,
                                         C, S, S, A, Otot, Ps[i], M);
    };

    // order so ncu (-s 5 -c 1) captures GEMM level 0 as launch #6
    prep(0);                                   // launches 1-2
    noop_kernel<<<1, 32>>>();                  // 3
    noop_kernel<<<1, 32>>>();                  // 4
    noop_kernel<<<1, 32>>>();                  // 5
    gemm(0);                                   // 6  <-- profiled
    for (int i = 1; i < 6; i++) prep(i);
    for (int i = 1; i < 6; i++) gemm(i);
}